// round 14
// baseline (speedup 1.0000x reference)
#include <cuda_runtime.h>
#include <cuda_bf16.h>
#include <math.h>
#include <stdint.h>

// Problem constants
#define BTOK 4096
#define NEXP 8
#define DIN  768
#define DH   2048
#define DOUT 768
#define TOPK 2
#define MP2   10240   // pair rows padded to 256-granularity (8192 + 8*256 max)
#define MT2   40      // m256 tiles
#define M16TOT 640    // m16 tiles
#define K16_1 48
#define K16_2 128

// ---------------- device globals (total ~115.5 MiB < 128 MiB granule) ----------------
__device__ uint4 g_a2fh[(size_t)M16TOT * K16_2 * 32];   // 41.9 MB
__device__ uint4 g_a2fl[(size_t)M16TOT * K16_2 * 32];   // 41.9 MB
#define A1F_BYTES 15728640  // M16TOT * K16_1 * 32 * 16
__device__ __align__(16) unsigned char g_union[(size_t)MP2 * DOUT * 4];  // 31.46 MB: A1 frags then z
__device__ float g_lse[MP2];
__device__ int   g_pair_token[MP2];
__device__ int   g_count[NEXP];
__device__ int   g_cursor[NEXP];
__device__ int   g_off[NEXP + 1];
__device__ int   g_mtile_expert[MT2];
__device__ int   g_n_mtiles;
__device__ int   g_tok_e[BTOK * TOPK];
__device__ float g_tok_g[BTOK * TOPK];
__device__ int   g_tok_p[BTOK * TOPK];

// ---------------- PTX helpers ----------------
__device__ __forceinline__ uint32_t smem_u32(const void* p) {
    uint32_t a;
    asm("{ .reg .u64 t; cvta.to.shared.u64 t, %1; cvt.u32.u64 %0, t; }" : "=r"(a) : "l"(p));
    return a;
}
__device__ __forceinline__ void lds128v(uint4& v, uint32_t a) {
    asm volatile("ld.shared.v4.u32 {%0,%1,%2,%3}, [%4];"
                 : "=r"(v.x), "=r"(v.y), "=r"(v.z), "=r"(v.w) : "r"(a));
}
__device__ __forceinline__ void lds64v(uint2& v, uint32_t a) {
    asm volatile("ld.shared.v2.u32 {%0,%1}, [%2];" : "=r"(v.x), "=r"(v.y) : "r"(a));
}
__device__ __forceinline__ void sts128v(uint32_t a, uint4 v) {
    asm volatile("st.shared.v4.u32 [%0], {%1,%2,%3,%4};"
                 :: "r"(a), "r"(v.x), "r"(v.y), "r"(v.z), "r"(v.w));
}
__device__ __forceinline__ void sts32(uint32_t a, uint32_t v) {
    asm volatile("st.shared.u32 [%0], %1;" :: "r"(a), "r"(v));
}
__device__ __forceinline__ void mma16816(float& c0, float& c1, float& c2, float& c3,
                                         uint32_t a0, uint32_t a1, uint32_t a2, uint32_t a3,
                                         uint32_t b0, uint32_t b1) {
    asm volatile("mma.sync.aligned.m16n8k16.row.col.f32.bf16.bf16.f32 "
                 "{%0,%1,%2,%3}, {%4,%5,%6,%7}, {%8,%9}, {%0,%1,%2,%3};"
                 : "+f"(c0), "+f"(c1), "+f"(c2), "+f"(c3)
                 : "r"(a0), "r"(a1), "r"(a2), "r"(a3), "r"(b0), "r"(b1));
}
__device__ __forceinline__ void hilo(float a, float b, uint32_t& h, uint32_t& l) {
    __nv_bfloat162 hh = __floats2bfloat162_rn(a, b);
    float2 hf = __bfloat1622float2(hh);
    __nv_bfloat162 ll = __floats2bfloat162_rn(a - hf.x, b - hf.y);
    h = *(uint32_t*)&hh;
    l = *(uint32_t*)&ll;
}
__device__ __forceinline__ float gelu_tanh(float v) {
    float v3 = v * v * v;
    return 0.5f * v * (1.0f + tanhf(0.7978845608028654f * (v + 0.044715f * v3)));
}

// smem (static 40,960 B): A-hi 16K | A-lo 16K | B-hi 4K | B-lo 4K (chunk = k32 x 256m x 64n)
#define AHI 0
#define ALO 16384
#define BHI 32768
#define BLO 36864

// ---------------- small kernels ----------------
__global__ void init_kernel() {
    int i = blockIdx.x * blockDim.x + threadIdx.x;
    if (i < MP2) g_pair_token[i] = -1;
    if (i < NEXP) { g_count[i] = 0; g_cursor[i] = 0; }
}

__global__ void gating_kernel(const float* __restrict__ x, const float* __restrict__ wg) {
    int gthread = blockIdx.x * blockDim.x + threadIdx.x;
    int warp = gthread >> 5, lane = gthread & 31;
    if (warp >= BTOK) return;
    const float* xr = x + (size_t)warp * DIN;
    float a0 = 0.f, a1 = 0.f, a2 = 0.f, a3 = 0.f, a4 = 0.f, a5 = 0.f, a6 = 0.f, a7 = 0.f;
    for (int i = lane; i < DIN; i += 32) {
        float xv = xr[i];
        const float4* wr = (const float4*)(wg + (size_t)i * NEXP);
        float4 w0 = wr[0], w1 = wr[1];
        a0 += xv * w0.x; a1 += xv * w0.y; a2 += xv * w0.z; a3 += xv * w0.w;
        a4 += xv * w1.x; a5 += xv * w1.y; a6 += xv * w1.z; a7 += xv * w1.w;
    }
#pragma unroll
    for (int off = 16; off > 0; off >>= 1) {
        a0 += __shfl_down_sync(0xFFFFFFFFu, a0, off);
        a1 += __shfl_down_sync(0xFFFFFFFFu, a1, off);
        a2 += __shfl_down_sync(0xFFFFFFFFu, a2, off);
        a3 += __shfl_down_sync(0xFFFFFFFFu, a3, off);
        a4 += __shfl_down_sync(0xFFFFFFFFu, a4, off);
        a5 += __shfl_down_sync(0xFFFFFFFFu, a5, off);
        a6 += __shfl_down_sync(0xFFFFFFFFu, a6, off);
        a7 += __shfl_down_sync(0xFFFFFFFFu, a7, off);
    }
    if (lane == 0) {
        float v0 = -3.402823466e38f, v1 = -3.402823466e38f;
        int e0 = 0, e1 = 0;
#define TOP2(val, idx) { float v = (val); if (v > v0) { v1 = v0; e1 = e0; v0 = v; e0 = idx; } else if (v > v1) { v1 = v; e1 = idx; } }
        TOP2(a0, 0) TOP2(a1, 1) TOP2(a2, 2) TOP2(a3, 3)
        TOP2(a4, 4) TOP2(a5, 5) TOP2(a6, 6) TOP2(a7, 7)
#undef TOP2
        float ex = expf(v1 - v0);
        float inv = 1.0f / (1.0f + ex);
        g_tok_e[warp * 2 + 0] = e0; g_tok_e[warp * 2 + 1] = e1;
        g_tok_g[warp * 2 + 0] = inv; g_tok_g[warp * 2 + 1] = ex * inv;
        atomicAdd(&g_count[e0], 1);
        atomicAdd(&g_count[e1], 1);
    }
}

__global__ void offsets_kernel() {
    if (threadIdx.x != 0 || blockIdx.x != 0) return;
    int off = 0, nt = 0;
    for (int e = 0; e < NEXP; e++) {
        g_off[e] = off;
        int c = g_count[e];
        int tiles = (c + 255) >> 8;
        for (int t = 0; t < tiles; t++) g_mtile_expert[nt + t] = e;
        nt += tiles;
        off += tiles << 8;
    }
    g_off[NEXP] = off;
    g_n_mtiles = nt;
}

__global__ void assign_kernel() {
    int t = blockIdx.x * blockDim.x + threadIdx.x;
    if (t >= BTOK) return;
#pragma unroll
    for (int s = 0; s < TOPK; s++) {
        int e = g_tok_e[t * 2 + s];
        int pos = atomicAdd(&g_cursor[e], 1);
        int p = g_off[e] + pos;
        g_pair_token[p] = t;
        g_tok_p[t * 2 + s] = p;
    }
}

// ---------------- gather_x: pair rows -> A1 fragments (hi/lo) in g_union ----------------
__global__ __launch_bounds__(256) void gather_x(const float* __restrict__ x) {
    __shared__ float s[16][260];
    uint4* a1fh = (uint4*)g_union;
    uint4* a1fl = (uint4*)(g_union + A1F_BYTES);
    int bt = blockIdx.x;  // m16 tile 0..639
    int t = threadIdx.x;
    int wi = t >> 5, lane = t & 31;
    int fr = lane >> 2, fk = (lane & 3) * 2;
    for (int c = 0; c < 3; c++) {
#pragma unroll
        for (int r = 0; r < 16; r++) {
            int tok = g_pair_token[bt * 16 + r];
            s[r][t] = (tok >= 0) ? x[(size_t)tok * DIN + c * 256 + t] : 0.f;
        }
        __syncthreads();
#pragma unroll
        for (int sub = 0; sub < 2; sub++) {
            int ktl = wi * 2 + sub;
            int kb = ktl * 16;
            uint4 H, L;
            hilo(s[fr][kb + fk], s[fr][kb + fk + 1], H.x, L.x);
            hilo(s[fr + 8][kb + fk], s[fr + 8][kb + fk + 1], H.y, L.y);
            hilo(s[fr][kb + fk + 8], s[fr][kb + fk + 9], H.z, L.z);
            hilo(s[fr + 8][kb + fk + 8], s[fr + 8][kb + fk + 9], H.w, L.w);
            size_t ad = ((size_t)bt * K16_1 + c * 16 + ktl) * 32 + lane;
            a1fh[ad] = H;
            a1fl[ad] = L;
        }
        __syncthreads();
    }
}

// ---------------- GEMM: CTA 256m x 64n, 256 thr, 8 warps 4(m)x2(n), warp tile 64x32 ----------------
// K-chunk 32 (2 k16 steps per sync). Pre-fragmented A + in-kernel W convert (amortized over 256 rows).
template<int K16T, int NBS, bool ISG1>
__global__ __launch_bounds__(256) void gemm_frag(const float* __restrict__ W,
                                                 const float* __restrict__ bias) {
    int mt = blockIdx.y;
    if (mt >= g_n_mtiles) return;
    int e = g_mtile_expert[mt];
    int col0 = blockIdx.x << 6;  // 64-wide N tile

    __shared__ __align__(16) unsigned char sm[40960];
    uint32_t sb = smem_u32(sm);
    int tid = threadIdx.x, w = tid >> 5, lane = tid & 31;
    int wm16 = (w >> 1) * 4;   // m16 tile base: 0/4/8/12
    int wn8 = (w & 1) * 4;     // n8 tile base: 0/4
    int wn = (w & 1) * 32;

    const uint4* Afh = ISG1 ? (const uint4*)g_union : g_a2fh;
    const uint4* Afl = ISG1 ? (const uint4*)(g_union + A1F_BYTES) : g_a2fl;
    float* zp = (float*)g_union;

    // A staging: thread covers tiles ai and ai+8 (ai = tid>>5), both j, one lane each
    int ai = tid >> 5;
    size_t aB0 = ((size_t)(mt * 16 + ai) * K16T) * 32 + lane;
    size_t aB1 = ((size_t)(mt * 16 + ai + 8) * K16T) * 32 + lane;
    uint32_t dA00 = (uint32_t)(ai * 1024 + lane * 16);          // (ai, j=0)
    uint32_t dA10 = (uint32_t)((ai + 8) * 1024 + lane * 16);    // (ai+8, j=0)

    // B staging: thread -> k-pair kp=(tid>>4)*2 (0..30), 4 n columns
    int kp = (tid >> 4) * 2;
    int nc = (tid & 15) * 4;
    int j_b = kp >> 4;
    int rem = kp & 15;
    uint32_t comp = (rem >= 8) ? 4u : 0u;
    int q = (rem & 7) >> 1;
    int btile = nc >> 3;
    int ncol_in = nc & 7;  // 0 or 4
    uint32_t dB = (uint32_t)(BHI + j_b * 2048 + btile * 256 + ncol_in * 32 + q * 8) + comp;
    const float* bw = W + ((size_t)e * (K16T * 16) + kp) * NBS + col0 + nc;

    // compute-phase bases
    uint32_t aF = sb + AHI + (uint32_t)(lane * 16);

#define DECL_ACC(mi, ni) float c##mi##ni##0 = 0.f, c##mi##ni##1 = 0.f, c##mi##ni##2 = 0.f, c##mi##ni##3 = 0.f;
    DECL_ACC(0, 0) DECL_ACC(0, 1) DECL_ACC(0, 2) DECL_ACC(0, 3)
    DECL_ACC(1, 0) DECL_ACC(1, 1) DECL_ACC(1, 2) DECL_ACC(1, 3)
    DECL_ACC(2, 0) DECL_ACC(2, 1) DECL_ACC(2, 2) DECL_ACC(2, 3)
    DECL_ACC(3, 0) DECL_ACC(3, 1) DECL_ACC(3, 2) DECL_ACC(3, 3)
#undef DECL_ACC

    uint4 pah00, pah01, pah10, pah11, pal00, pal01, pal10, pal11;
    float4 pb0, pb1;
#define PREFETCH(ck) do { \
    pah00 = Afh[aB0 + ((ck) * 2 + 0) * 32]; pah01 = Afh[aB0 + ((ck) * 2 + 1) * 32]; \
    pah10 = Afh[aB1 + ((ck) * 2 + 0) * 32]; pah11 = Afh[aB1 + ((ck) * 2 + 1) * 32]; \
    pal00 = Afl[aB0 + ((ck) * 2 + 0) * 32]; pal01 = Afl[aB0 + ((ck) * 2 + 1) * 32]; \
    pal10 = Afl[aB1 + ((ck) * 2 + 0) * 32]; pal11 = Afl[aB1 + ((ck) * 2 + 1) * 32]; \
    const float* p_ = bw + (size_t)(ck) * 32 * NBS; \
    pb0 = *(const float4*)(p_); \
    pb1 = *(const float4*)(p_ + NBS); \
} while (0)
#define BSTS(i, va, vb) do { \
    uint32_t h_, l_; hilo(va, vb, h_, l_); \
    sts32(sb + dB + (i) * 32, h_); \
    sts32(sb + dB + (BLO - BHI) + (i) * 32, l_); \
} while (0)
#define STAGE() do { \
    sts128v(sb + dA00, pah00);       sts128v(sb + dA00 + 512, pah01); \
    sts128v(sb + dA10, pah10);       sts128v(sb + dA10 + 512, pah11); \
    sts128v(sb + dA00 + ALO, pal00); sts128v(sb + dA00 + ALO + 512, pal01); \
    sts128v(sb + dA10 + ALO, pal10); sts128v(sb + dA10 + ALO + 512, pal11); \
    BSTS(0, pb0.x, pb1.x); BSTS(1, pb0.y, pb1.y); \
    BSTS(2, pb0.z, pb1.z); BSTS(3, pb0.w, pb1.w); \
} while (0)
#define MMA3(mi, ni) \
    mma16816(c##mi##ni##0, c##mi##ni##1, c##mi##ni##2, c##mi##ni##3, \
             ah##mi.x, ah##mi.y, ah##mi.z, ah##mi.w, bh##ni.x, bh##ni.y); \
    mma16816(c##mi##ni##0, c##mi##ni##1, c##mi##ni##2, c##mi##ni##3, \
             ah##mi.x, ah##mi.y, ah##mi.z, ah##mi.w, bl##ni.x, bl##ni.y); \
    mma16816(c##mi##ni##0, c##mi##ni##1, c##mi##ni##2, c##mi##ni##3, \
             al##mi.x, al##mi.y, al##mi.z, al##mi.w, bh##ni.x, bh##ni.y);
#define COMPUTE_J(j) do { \
    uint4 ah0, ah1, ah2, ah3, al0, al1, al2, al3; \
    uint2 bh0, bh1, bh2, bh3, bl0, bl1, bl2, bl3; \
    lds128v(ah0, aF + ((wm16 + 0) * 2 + (j)) * 512); \
    lds128v(ah1, aF + ((wm16 + 1) * 2 + (j)) * 512); \
    lds128v(ah2, aF + ((wm16 + 2) * 2 + (j)) * 512); \
    lds128v(ah3, aF + ((wm16 + 3) * 2 + (j)) * 512); \
    lds128v(al0, aF + ALO + ((wm16 + 0) * 2 + (j)) * 512); \
    lds128v(al1, aF + ALO + ((wm16 + 1) * 2 + (j)) * 512); \
    lds128v(al2, aF + ALO + ((wm16 + 2) * 2 + (j)) * 512); \
    lds128v(al3, aF + ALO + ((wm16 + 3) * 2 + (j)) * 512); \
    uint32_t bF_ = sb + BHI + (uint32_t)((j) * 2048 + lane * 8); \
    lds64v(bh0, bF_ + (wn8 + 0) * 256); \
    lds64v(bh1, bF_ + (wn8 + 1) * 256); \
    lds64v(bh2, bF_ + (wn8 + 2) * 256); \
    lds64v(bh3, bF_ + (wn8 + 3) * 256); \
    lds64v(bl0, bF_ + (BLO - BHI) + (wn8 + 0) * 256); \
    lds64v(bl1, bF_ + (BLO - BHI) + (wn8 + 1) * 256); \
    lds64v(bl2, bF_ + (BLO - BHI) + (wn8 + 2) * 256); \
    lds64v(bl3, bF_ + (BLO - BHI) + (wn8 + 3) * 256); \
    MMA3(0, 0) MMA3(0, 1) MMA3(0, 2) MMA3(0, 3) \
    MMA3(1, 0) MMA3(1, 1) MMA3(1, 2) MMA3(1, 3) \
    MMA3(2, 0) MMA3(2, 1) MMA3(2, 2) MMA3(2, 3) \
    MMA3(3, 0) MMA3(3, 1) MMA3(3, 2) MMA3(3, 3) \
} while (0)

    const int NC = K16T / 2;
    PREFETCH(0);
    for (int ck = 0; ck < NC; ck++) {
        STAGE();
        __syncthreads();
        if (ck + 1 < NC) PREFETCH(ck + 1);
        COMPUTE_J(0);
        COMPUTE_J(1);
        __syncthreads();
    }
#undef PREFETCH
#undef BSTS
#undef STAGE
#undef COMPUTE_J
#undef MMA3

    // ---- epilogue ----
    int er = lane >> 2;
    int ec = (lane & 3) * 2;
#define EPI(mi) do { \
    if (ISG1) { \
        size_t m16o = (size_t)(mt * 16 + wm16 + (mi)); \
        int gc0 = col0 + wn + ec; \
        { \
            float bE0 = __ldg(bias + (size_t)e * DH + gc0); \
            float bE1 = __ldg(bias + (size_t)e * DH + gc0 + 1); \
            float bO0 = __ldg(bias + (size_t)e * DH + gc0 + 8); \
            float bO1 = __ldg(bias + (size_t)e * DH + gc0 + 9); \
            uint4 H, L; \
            hilo(gelu_tanh(c##mi##00 + bE0), gelu_tanh(c##mi##01 + bE1), H.x, L.x); \
            hilo(gelu_tanh(c##mi##02 + bE0), gelu_tanh(c##mi##03 + bE1), H.y, L.y); \
            hilo(gelu_tanh(c##mi##10 + bO0), gelu_tanh(c##mi##11 + bO1), H.z, L.z); \
            hilo(gelu_tanh(c##mi##12 + bO0), gelu_tanh(c##mi##13 + bO1), H.w, L.w); \
            size_t ad = (m16o * K16_2 + (size_t)((col0 + wn) >> 4)) * 32 + lane; \
            g_a2fh[ad] = H; g_a2fl[ad] = L; \
        } \
        { \
            float bE0 = __ldg(bias + (size_t)e * DH + gc0 + 16); \
            float bE1 = __ldg(bias + (size_t)e * DH + gc0 + 17); \
            float bO0 = __ldg(bias + (size_t)e * DH + gc0 + 24); \
            float bO1 = __ldg(bias + (size_t)e * DH + gc0 + 25); \
            uint4 H, L; \
            hilo(gelu_tanh(c##mi##20 + bE0), gelu_tanh(c##mi##21 + bE1), H.x, L.x); \
            hilo(gelu_tanh(c##mi##22 + bE0), gelu_tanh(c##mi##23 + bE1), H.y, L.y); \
            hilo(gelu_tanh(c##mi##30 + bO0), gelu_tanh(c##mi##31 + bO1), H.z, L.z); \
            hilo(gelu_tanh(c##mi##32 + bO0), gelu_tanh(c##mi##33 + bO1), H.w, L.w); \
            size_t ad = (m16o * K16_2 + (size_t)(((col0 + wn) >> 4) + 1)) * 32 + lane; \
            g_a2fh[ad] = H; g_a2fl[ad] = L; \
        } \
    } else { \
        int rb = mt * 256 + (wm16 + (mi)) * 16 + er; \
        int gcb = col0 + wn + ec; \
        float b0v = __ldg(bias + (size_t)e * DOUT + gcb); \
        float b1v = __ldg(bias + (size_t)e * DOUT + gcb + 1); \
        float b8v = __ldg(bias + (size_t)e * DOUT + gcb + 8); \
        float b9v = __ldg(bias + (size_t)e * DOUT + gcb + 9); \
        float b16v = __ldg(bias + (size_t)e * DOUT + gcb + 16); \
        float b17v = __ldg(bias + (size_t)e * DOUT + gcb + 17); \
        float b24v = __ldg(bias + (size_t)e * DOUT + gcb + 24); \
        float b25v = __ldg(bias + (size_t)e * DOUT + gcb + 25); \
        float2 o; \
        o.x = c##mi##00 + b0v;  o.y = c##mi##01 + b1v;  *(float2*)(zp + (size_t)rb * DOUT + gcb) = o; \
        o.x = c##mi##02 + b0v;  o.y = c##mi##03 + b1v;  *(float2*)(zp + (size_t)(rb + 8) * DOUT + gcb) = o; \
        o.x = c##mi##10 + b8v;  o.y = c##mi##11 + b9v;  *(float2*)(zp + (size_t)rb * DOUT + gcb + 8) = o; \
        o.x = c##mi##12 + b8v;  o.y = c##mi##13 + b9v;  *(float2*)(zp + (size_t)(rb + 8) * DOUT + gcb + 8) = o; \
        o.x = c##mi##20 + b16v; o.y = c##mi##21 + b17v; *(float2*)(zp + (size_t)rb * DOUT + gcb + 16) = o; \
        o.x = c##mi##22 + b16v; o.y = c##mi##23 + b17v; *(float2*)(zp + (size_t)(rb + 8) * DOUT + gcb + 16) = o; \
        o.x = c##mi##30 + b24v; o.y = c##mi##31 + b25v; *(float2*)(zp + (size_t)rb * DOUT + gcb + 24) = o; \
        o.x = c##mi##32 + b24v; o.y = c##mi##33 + b25v; *(float2*)(zp + (size_t)(rb + 8) * DOUT + gcb + 24) = o; \
    } \
} while (0)
    EPI(0); EPI(1); EPI(2); EPI(3);
#undef EPI
}

// ---------------- logsumexp / combine / loss (z lives in g_union) ----------------
__global__ __launch_bounds__(256) void lse_kernel() {
    int p = blockIdx.x;
    if (g_pair_token[p] < 0) return;
    const float* row = (const float*)g_union + (size_t)p * DOUT;
    int tid = threadIdx.x;
    __shared__ float sred[256];
    float m = fmaxf(fmaxf(row[tid], row[tid + 256]), row[tid + 512]);
    sred[tid] = m;
    __syncthreads();
    for (int st = 128; st > 0; st >>= 1) {
        if (tid < st) sred[tid] = fmaxf(sred[tid], sred[tid + st]);
        __syncthreads();
    }
    float rmax = sred[0];
    __syncthreads();
    float s = expf(row[tid] - rmax) + expf(row[tid + 256] - rmax) + expf(row[tid + 512] - rmax);
    sred[tid] = s;
    __syncthreads();
    for (int st = 128; st > 0; st >>= 1) {
        if (tid < st) sred[tid] += sred[tid + st];
        __syncthreads();
    }
    if (tid == 0) g_lse[p] = rmax + logf(sred[0]);
}

__global__ __launch_bounds__(256) void combine_kernel(float* __restrict__ out) {
    const float* zp = (const float*)g_union;
    int b = blockIdx.y;
    int o = blockIdx.x * 256 + threadIdx.x;
    int p0 = g_tok_p[b * 2 + 0], p1 = g_tok_p[b * 2 + 1];
    float g0 = g_tok_g[b * 2 + 0], g1 = g_tok_g[b * 2 + 1];
    float lse0 = g_lse[p0], lse1 = g_lse[p1];
    float z0 = zp[(size_t)p0 * DOUT + o];
    float z1 = zp[(size_t)p1 * DOUT + o];
    float c = g0 * expf(z0 - lse0) + g1 * expf(z1 - lse1);
    if (c == 0.0f) c = 2.2204460492503131e-16f;
    out[(size_t)b * DOUT + o] = logf(c);
}

__global__ __launch_bounds__(256) void loss_kernel(float* __restrict__ out, int write_loss) {
    __shared__ float simp[NEXP][257];
    int tid = threadIdx.x;
#pragma unroll
    for (int e = 0; e < NEXP; e++) simp[e][tid] = 0.f;
    __syncthreads();
    for (int t = tid; t < BTOK; t += 256) {
        simp[g_tok_e[t * 2 + 0]][tid] += g_tok_g[t * 2 + 0];
        simp[g_tok_e[t * 2 + 1]][tid] += g_tok_g[t * 2 + 1];
    }
    __syncthreads();
    for (int st = 128; st > 0; st >>= 1) {
        if (tid < st)
#pragma unroll
            for (int e = 0; e < NEXP; e++) simp[e][tid] += simp[e][tid + st];
        __syncthreads();
    }
    if (tid == 0 && write_loss) {
        float mi = 0.f, ml = 0.f;
        for (int e = 0; e < NEXP; e++) { mi += simp[e][0]; ml += (float)g_cursor[e]; }
        mi /= NEXP; ml /= NEXP;
        float si = 0.f, sl = 0.f;
        for (int e = 0; e < NEXP; e++) {
            float di = simp[e][0] - mi;
            float dl = (float)g_cursor[e] - ml;
            si += di * di;
            sl += dl * dl;
        }
        si /= (NEXP - 1); sl /= (NEXP - 1);
        out[(size_t)BTOK * DOUT] = 0.01f * (si / (mi * mi + 1e-10f) + sl / (ml * ml + 1e-10f));
    }
}

// ---------------- launch ----------------
extern "C" void kernel_launch(void* const* d_in, const int* in_sizes, int n_in,
                              void* d_out, int out_size) {
    const float* x  = (const float*)d_in[0];
    const float* wg = (const float*)d_in[1];
    const float* W1 = (const float*)d_in[2];
    const float* b1 = (const float*)d_in[3];
    const float* W2 = (const float*)d_in[4];
    const float* b2 = (const float*)d_in[5];
    float* out = (float*)d_out;

    int write_loss = (out_size > BTOK * DOUT) ? 1 : 0;

    init_kernel<<<(MP2 + 255) / 256, 256>>>();
    gating_kernel<<<(BTOK * 32 + 255) / 256, 256>>>(x, wg);
    offsets_kernel<<<1, 1>>>();
    assign_kernel<<<(BTOK + 255) / 256, 256>>>();
    gather_x<<<M16TOT, 256>>>(x);
    gemm_frag<K16_1, DH, true><<<dim3(DH / 64, MT2), 256>>>(W1, b1);
    gemm_frag<K16_2, DOUT, false><<<dim3(DOUT / 64, MT2), 256>>>(W2, b2);
    lse_kernel<<<MP2, 256>>>();
    combine_kernel<<<dim3(DOUT / 256, BTOK), 256>>>(out);
    loss_kernel<<<1, 256>>>(out, write_loss);
}

// round 15
// speedup vs baseline: 1.5723x; 1.5723x over previous
#include <cuda_runtime.h>
#include <cuda_fp16.h>
#include <math.h>
#include <stdint.h>

// Problem constants
#define BTOK 4096
#define NEXP 8
#define DIN  768
#define DH   2048
#define DOUT 768
#define TOPK 2
#define MAXPAIR 9216
#define MAXMT   72
#define K16_1 48    // DIN/16
#define K16_2 128   // DH/16

// ---------------- device globals: TOTAL < 128 MiB (driver granule); NO cp.async/ldmatrix ----------------
__device__ uint4 g_a2fh[(size_t)(MAXPAIR / 16) * K16_2 * 32];
__device__ uint4 g_a2fl[(size_t)(MAXPAIR / 16) * K16_2 * 32];
#define A1F_BYTES 14155776  // (MAXPAIR/16) * K16_1 * 32 * 16
__device__ __align__(16) unsigned char g_union[(size_t)MAXPAIR * DOUT * 4];  // A1 frags, then z
__device__ float g_lse[MAXPAIR];
__device__ int   g_pair_token[MAXPAIR];
__device__ int   g_count[NEXP];
__device__ int   g_cursor[NEXP];
__device__ int   g_off[NEXP + 1];
__device__ int   g_mtile_expert[MAXMT];
__device__ int   g_n_mtiles;
__device__ int   g_tok_e[BTOK * TOPK];
__device__ float g_tok_g[BTOK * TOPK];
__device__ int   g_tok_p[BTOK * TOPK];

// ---------------- PTX helpers ----------------
__device__ __forceinline__ uint32_t smem_u32(const void* p) {
    uint32_t a;
    asm("{ .reg .u64 t; cvta.to.shared.u64 t, %1; cvt.u32.u64 %0, t; }" : "=r"(a) : "l"(p));
    return a;
}
__device__ __forceinline__ void lds128v(uint4& v, uint32_t a) {
    asm volatile("ld.shared.v4.u32 {%0,%1,%2,%3}, [%4];"
                 : "=r"(v.x), "=r"(v.y), "=r"(v.z), "=r"(v.w) : "r"(a));
}
__device__ __forceinline__ void lds64v(uint2& v, uint32_t a) {
    asm volatile("ld.shared.v2.u32 {%0,%1}, [%2];" : "=r"(v.x), "=r"(v.y) : "r"(a));
}
__device__ __forceinline__ void sts128v(uint32_t a, uint4 v) {
    asm volatile("st.shared.v4.u32 [%0], {%1,%2,%3,%4};"
                 :: "r"(a), "r"(v.x), "r"(v.y), "r"(v.z), "r"(v.w));
}
__device__ __forceinline__ void sts32(uint32_t a, uint32_t v) {
    asm volatile("st.shared.u32 [%0], %1;" :: "r"(a), "r"(v));
}
// fp16 MMA: m16n8k16, fp32 accum
__device__ __forceinline__ void mma16816(float& c0, float& c1, float& c2, float& c3,
                                         uint32_t a0, uint32_t a1, uint32_t a2, uint32_t a3,
                                         uint32_t b0, uint32_t b1) {
    asm volatile("mma.sync.aligned.m16n8k16.row.col.f32.f16.f16.f32 "
                 "{%0,%1,%2,%3}, {%4,%5,%6,%7}, {%8,%9}, {%0,%1,%2,%3};"
                 : "+f"(c0), "+f"(c1), "+f"(c2), "+f"(c3)
                 : "r"(a0), "r"(a1), "r"(a2), "r"(a3), "r"(b0), "r"(b1));
}
// fp16 hi/lo split (A-side): hi = rn(v), lo = rn(v - hi) -> ~22 mantissa bits combined
__device__ __forceinline__ void hilo16(float a, float b, uint32_t& h, uint32_t& l) {
    __half2 hh = __floats2half2_rn(a, b);
    float2 hf = __half22float2(hh);
    __half2 ll = __floats2half2_rn(a - hf.x, b - hf.y);
    h = *(uint32_t*)&hh;
    l = *(uint32_t*)&ll;
}
__device__ __forceinline__ uint32_t pack16(float a, float b) {
    __half2 hh = __floats2half2_rn(a, b);
    return *(uint32_t*)&hh;
}
__device__ __forceinline__ float gelu_tanh(float v) {
    float v3 = v * v * v;
    return 0.5f * v * (1.0f + tanhf(0.7978845608028654f * (v + 0.044715f * v3)));
}

// smem (static 24,832 B): A-hi 8K | A-lo 8K | B 8448 (single fp16)
#define AHI 0
#define ALO 8192
#define BHI 16384
#define B_TILE_STRIDE 264
#define B_J_STRIDE 4224

// ---------------- small kernels ----------------
__global__ void init_kernel() {
    int i = blockIdx.x * blockDim.x + threadIdx.x;
    if (i < MAXPAIR) g_pair_token[i] = -1;
    if (i < NEXP) { g_count[i] = 0; g_cursor[i] = 0; }
}

__global__ void gating_kernel(const float* __restrict__ x, const float* __restrict__ wg) {
    int gthread = blockIdx.x * blockDim.x + threadIdx.x;
    int warp = gthread >> 5, lane = gthread & 31;
    if (warp >= BTOK) return;
    const float* xr = x + (size_t)warp * DIN;
    float a0 = 0.f, a1 = 0.f, a2 = 0.f, a3 = 0.f, a4 = 0.f, a5 = 0.f, a6 = 0.f, a7 = 0.f;
    for (int i = lane; i < DIN; i += 32) {
        float xv = xr[i];
        const float4* wr = (const float4*)(wg + (size_t)i * NEXP);
        float4 w0 = wr[0], w1 = wr[1];
        a0 += xv * w0.x; a1 += xv * w0.y; a2 += xv * w0.z; a3 += xv * w0.w;
        a4 += xv * w1.x; a5 += xv * w1.y; a6 += xv * w1.z; a7 += xv * w1.w;
    }
#pragma unroll
    for (int off = 16; off > 0; off >>= 1) {
        a0 += __shfl_down_sync(0xFFFFFFFFu, a0, off);
        a1 += __shfl_down_sync(0xFFFFFFFFu, a1, off);
        a2 += __shfl_down_sync(0xFFFFFFFFu, a2, off);
        a3 += __shfl_down_sync(0xFFFFFFFFu, a3, off);
        a4 += __shfl_down_sync(0xFFFFFFFFu, a4, off);
        a5 += __shfl_down_sync(0xFFFFFFFFu, a5, off);
        a6 += __shfl_down_sync(0xFFFFFFFFu, a6, off);
        a7 += __shfl_down_sync(0xFFFFFFFFu, a7, off);
    }
    if (lane == 0) {
        float v0 = -3.402823466e38f, v1 = -3.402823466e38f;
        int e0 = 0, e1 = 0;
#define TOP2(val, idx) { float v = (val); if (v > v0) { v1 = v0; e1 = e0; v0 = v; e0 = idx; } else if (v > v1) { v1 = v; e1 = idx; } }
        TOP2(a0, 0) TOP2(a1, 1) TOP2(a2, 2) TOP2(a3, 3)
        TOP2(a4, 4) TOP2(a5, 5) TOP2(a6, 6) TOP2(a7, 7)
#undef TOP2
        float ex = expf(v1 - v0);
        float inv = 1.0f / (1.0f + ex);
        g_tok_e[warp * 2 + 0] = e0; g_tok_e[warp * 2 + 1] = e1;
        g_tok_g[warp * 2 + 0] = inv; g_tok_g[warp * 2 + 1] = ex * inv;
        atomicAdd(&g_count[e0], 1);
        atomicAdd(&g_count[e1], 1);
    }
}

__global__ void offsets_kernel() {
    if (threadIdx.x != 0 || blockIdx.x != 0) return;
    int off = 0, nt = 0;
    for (int e = 0; e < NEXP; e++) {
        g_off[e] = off;
        int c = g_count[e];
        int tiles = (c + 127) >> 7;
        for (int t = 0; t < tiles; t++) g_mtile_expert[nt + t] = e;
        nt += tiles;
        off += tiles << 7;
    }
    g_off[NEXP] = off;
    g_n_mtiles = nt;
}

__global__ void assign_kernel() {
    int t = blockIdx.x * blockDim.x + threadIdx.x;
    if (t >= BTOK) return;
#pragma unroll
    for (int s = 0; s < TOPK; s++) {
        int e = g_tok_e[t * 2 + s];
        int pos = atomicAdd(&g_cursor[e], 1);
        int p = g_off[e] + pos;
        g_pair_token[p] = t;
        g_tok_p[t * 2 + s] = p;
    }
}

// ---------------- gather_x: pair rows -> A1 fp16 hi/lo fragments in g_union ----------------
__global__ __launch_bounds__(256) void gather_x(const float* __restrict__ x) {
    __shared__ float s[16][260];
    uint4* a1fh = (uint4*)g_union;
    uint4* a1fl = (uint4*)(g_union + A1F_BYTES);
    int bt = blockIdx.x;
    int t = threadIdx.x;
    int wi = t >> 5, lane = t & 31;
    int fr = lane >> 2, fk = (lane & 3) * 2;
    for (int c = 0; c < 3; c++) {
#pragma unroll
        for (int r = 0; r < 16; r++) {
            int tok = g_pair_token[bt * 16 + r];
            s[r][t] = (tok >= 0) ? x[(size_t)tok * DIN + c * 256 + t] : 0.f;
        }
        __syncthreads();
#pragma unroll
        for (int sub = 0; sub < 2; sub++) {
            int ktl = wi * 2 + sub;
            int kb = ktl * 16;
            uint4 H, L;
            hilo16(s[fr][kb + fk], s[fr][kb + fk + 1], H.x, L.x);
            hilo16(s[fr + 8][kb + fk], s[fr + 8][kb + fk + 1], H.y, L.y);
            hilo16(s[fr][kb + fk + 8], s[fr][kb + fk + 9], H.z, L.z);
            hilo16(s[fr + 8][kb + fk + 8], s[fr + 8][kb + fk + 9], H.w, L.w);
            size_t ad = ((size_t)bt * K16_1 + c * 16 + ktl) * 32 + lane;
            a1fh[ad] = H;
            a1fl[ad] = L;
        }
        __syncthreads();
    }
}

// ---------------- GEMM: 512 threads, 16 warps 4(m)x4(n), warp tile 32x32, fp16 2-term ----------------
template<int K16T, int NB, bool ISG1>
__global__ __launch_bounds__(512) void gemm_frag(const float* __restrict__ W,
                                                 const float* __restrict__ bias) {
    int mt = blockIdx.y;
    if (mt >= g_n_mtiles) return;
    int e = g_mtile_expert[mt];
    int col0 = blockIdx.x << 7;

    __shared__ __align__(16) unsigned char sm[24832];
    uint32_t sb = smem_u32(sm);
    int tid = threadIdx.x, w = tid >> 5, lane = tid & 31;
    int wm16 = (w >> 2) * 2;   // m16 tile base (0/2/4/6)
    int wn8 = (w & 3) * 4;     // n8 tile base
    int wn = (w & 3) * 32;

    const uint4* Afh = ISG1 ? (const uint4*)g_union : g_a2fh;
    const uint4* Afl = ISG1 ? (const uint4*)(g_union + A1F_BYTES) : g_a2fl;
    float* zp = (float*)g_union;

    // A staging: thread t covers uint4 #t of the chunk's 512 hi (and lo) fragments
    int ai = tid >> 6, j_a = (tid >> 5) & 1;
    size_t aB = ((size_t)(mt * 8 + ai) * K16T + j_a) * 32 + (tid & 31);
    uint32_t dA = (uint32_t)(tid * 16);

    // B staging: thread -> k-pair kp=(tid>>5)*2 (0..30), 4 n columns (single fp16)
    int kp = (tid >> 5) * 2;
    int nseg4 = tid & 31;
    int nt = nseg4 >> 1;
    int ncol0 = (nseg4 & 1) * 4;
    int j_b = kp >> 4;
    int rem = kp & 15;
    uint32_t comp = (rem >= 8) ? 4u : 0u;
    int lq = (rem & 7) >> 1;
    uint32_t dB = (uint32_t)(BHI + j_b * B_J_STRIDE + nt * B_TILE_STRIDE + ncol0 * 32 + lq * 8) + comp;
    const float* bw = W + ((size_t)e * (K16T * 16) + kp) * NB + col0 + nt * 8 + ncol0;

    // compute-phase bases
    uint32_t aF = sb + AHI + (uint32_t)(lane * 16);
    uint32_t bF = sb + BHI + (uint32_t)(lane * 8);

#define DECL_ACC(mi, ni) float c##mi##ni##0 = 0.f, c##mi##ni##1 = 0.f, c##mi##ni##2 = 0.f, c##mi##ni##3 = 0.f;
    DECL_ACC(0, 0) DECL_ACC(0, 1) DECL_ACC(0, 2) DECL_ACC(0, 3)
    DECL_ACC(1, 0) DECL_ACC(1, 1) DECL_ACC(1, 2) DECL_ACC(1, 3)
#undef DECL_ACC

    uint4 pah, pal;
    float4 pb0, pb1;
#define PREFETCH(ck) do { \
    pah = Afh[aB + (size_t)(ck) * 64]; \
    pal = Afl[aB + (size_t)(ck) * 64]; \
    const float* p_ = bw + (size_t)(ck) * 32 * NB; \
    pb0 = *(const float4*)(p_); \
    pb1 = *(const float4*)(p_ + NB); \
} while (0)
#define BSTS(i, va, vb) sts32(sb + dB + (i) * 32, pack16(va, vb))
#define STAGE() do { \
    sts128v(sb + dA, pah); \
    sts128v(sb + dA + ALO, pal); \
    BSTS(0, pb0.x, pb1.x); BSTS(1, pb0.y, pb1.y); \
    BSTS(2, pb0.z, pb1.z); BSTS(3, pb0.w, pb1.w); \
} while (0)
#define MMA2(mi, ni) \
    mma16816(c##mi##ni##0, c##mi##ni##1, c##mi##ni##2, c##mi##ni##3, \
             ah##mi.x, ah##mi.y, ah##mi.z, ah##mi.w, bh##ni.x, bh##ni.y); \
    mma16816(c##mi##ni##0, c##mi##ni##1, c##mi##ni##2, c##mi##ni##3, \
             al##mi.x, al##mi.y, al##mi.z, al##mi.w, bh##ni.x, bh##ni.y);
#define COMPUTE_J(j) do { \
    uint4 ah0, ah1, al0, al1; \
    uint2 bh0, bh1, bh2, bh3; \
    lds128v(ah0, aF + ((wm16 + 0) * 2 + (j)) * 512); \
    lds128v(ah1, aF + ((wm16 + 1) * 2 + (j)) * 512); \
    lds128v(al0, aF + ALO + ((wm16 + 0) * 2 + (j)) * 512); \
    lds128v(al1, aF + ALO + ((wm16 + 1) * 2 + (j)) * 512); \
    lds64v(bh0, bF + (j) * B_J_STRIDE + (wn8 + 0) * B_TILE_STRIDE); \
    lds64v(bh1, bF + (j) * B_J_STRIDE + (wn8 + 1) * B_TILE_STRIDE); \
    lds64v(bh2, bF + (j) * B_J_STRIDE + (wn8 + 2) * B_TILE_STRIDE); \
    lds64v(bh3, bF + (j) * B_J_STRIDE + (wn8 + 3) * B_TILE_STRIDE); \
    MMA2(0, 0) MMA2(0, 1) MMA2(0, 2) MMA2(0, 3) \
    MMA2(1, 0) MMA2(1, 1) MMA2(1, 2) MMA2(1, 3) \
} while (0)

    const int NC = K16T / 2;
    PREFETCH(0);
    for (int ck = 0; ck < NC; ck++) {
        STAGE();
        __syncthreads();
        if (ck + 1 < NC) PREFETCH(ck + 1);
        COMPUTE_J(0);
        COMPUTE_J(1);
        __syncthreads();
    }
#undef PREFETCH
#undef BSTS
#undef STAGE
#undef COMPUTE_J
#undef MMA2

    // ---- epilogue ----
    int er = lane >> 2;
    int ec = (lane & 3) * 2;
#define EPI(mi) do { \
    if (ISG1) { \
        size_t m16o = (size_t)(mt * 8 + wm16 + (mi)); \
        int gc0 = col0 + wn + ec; \
        { \
            float bE0 = __ldg(bias + (size_t)e * DH + gc0); \
            float bE1 = __ldg(bias + (size_t)e * DH + gc0 + 1); \
            float bO0 = __ldg(bias + (size_t)e * DH + gc0 + 8); \
            float bO1 = __ldg(bias + (size_t)e * DH + gc0 + 9); \
            uint4 H, L; \
            hilo16(gelu_tanh(c##mi##00 + bE0), gelu_tanh(c##mi##01 + bE1), H.x, L.x); \
            hilo16(gelu_tanh(c##mi##02 + bE0), gelu_tanh(c##mi##03 + bE1), H.y, L.y); \
            hilo16(gelu_tanh(c##mi##10 + bO0), gelu_tanh(c##mi##11 + bO1), H.z, L.z); \
            hilo16(gelu_tanh(c##mi##12 + bO0), gelu_tanh(c##mi##13 + bO1), H.w, L.w); \
            size_t ad = (m16o * K16_2 + (size_t)((col0 + wn) >> 4)) * 32 + lane; \
            g_a2fh[ad] = H; g_a2fl[ad] = L; \
        } \
        { \
            float bE0 = __ldg(bias + (size_t)e * DH + gc0 + 16); \
            float bE1 = __ldg(bias + (size_t)e * DH + gc0 + 17); \
            float bO0 = __ldg(bias + (size_t)e * DH + gc0 + 24); \
            float bO1 = __ldg(bias + (size_t)e * DH + gc0 + 25); \
            uint4 H, L; \
            hilo16(gelu_tanh(c##mi##20 + bE0), gelu_tanh(c##mi##21 + bE1), H.x, L.x); \
            hilo16(gelu_tanh(c##mi##22 + bE0), gelu_tanh(c##mi##23 + bE1), H.y, L.y); \
            hilo16(gelu_tanh(c##mi##30 + bO0), gelu_tanh(c##mi##31 + bO1), H.z, L.z); \
            hilo16(gelu_tanh(c##mi##32 + bO0), gelu_tanh(c##mi##33 + bO1), H.w, L.w); \
            size_t ad = (m16o * K16_2 + (size_t)(((col0 + wn) >> 4) + 1)) * 32 + lane; \
            g_a2fh[ad] = H; g_a2fl[ad] = L; \
        } \
    } else { \
        int rb = mt * 128 + (wm16 + (mi)) * 16 + er; \
        int gcb = col0 + wn + ec; \
        float b0v = __ldg(bias + (size_t)e * DOUT + gcb); \
        float b1v = __ldg(bias + (size_t)e * DOUT + gcb + 1); \
        float b8v = __ldg(bias + (size_t)e * DOUT + gcb + 8); \
        float b9v = __ldg(bias + (size_t)e * DOUT + gcb + 9); \
        float b16v = __ldg(bias + (size_t)e * DOUT + gcb + 16); \
        float b17v = __ldg(bias + (size_t)e * DOUT + gcb + 17); \
        float b24v = __ldg(bias + (size_t)e * DOUT + gcb + 24); \
        float b25v = __ldg(bias + (size_t)e * DOUT + gcb + 25); \
        float2 o; \
        o.x = c##mi##00 + b0v;  o.y = c##mi##01 + b1v;  *(float2*)(zp + (size_t)rb * DOUT + gcb) = o; \
        o.x = c##mi##02 + b0v;  o.y = c##mi##03 + b1v;  *(float2*)(zp + (size_t)(rb + 8) * DOUT + gcb) = o; \
        o.x = c##mi##10 + b8v;  o.y = c##mi##11 + b9v;  *(float2*)(zp + (size_t)rb * DOUT + gcb + 8) = o; \
        o.x = c##mi##12 + b8v;  o.y = c##mi##13 + b9v;  *(float2*)(zp + (size_t)(rb + 8) * DOUT + gcb + 8) = o; \
        o.x = c##mi##20 + b16v; o.y = c##mi##21 + b17v; *(float2*)(zp + (size_t)rb * DOUT + gcb + 16) = o; \
        o.x = c##mi##22 + b16v; o.y = c##mi##23 + b17v; *(float2*)(zp + (size_t)(rb + 8) * DOUT + gcb + 16) = o; \
        o.x = c##mi##30 + b24v; o.y = c##mi##31 + b25v; *(float2*)(zp + (size_t)rb * DOUT + gcb + 24) = o; \
        o.x = c##mi##32 + b24v; o.y = c##mi##33 + b25v; *(float2*)(zp + (size_t)(rb + 8) * DOUT + gcb + 24) = o; \
    } \
} while (0)
    EPI(0); EPI(1);
#undef EPI
}

// ---------------- logsumexp / combine / loss (z lives in g_union) ----------------
__global__ __launch_bounds__(256) void lse_kernel() {
    int p = blockIdx.x;
    if (g_pair_token[p] < 0) return;
    const float* row = (const float*)g_union + (size_t)p * DOUT;
    int tid = threadIdx.x;
    __shared__ float sred[256];
    float m = fmaxf(fmaxf(row[tid], row[tid + 256]), row[tid + 512]);
    sred[tid] = m;
    __syncthreads();
    for (int st = 128; st > 0; st >>= 1) {
        if (tid < st) sred[tid] = fmaxf(sred[tid], sred[tid + st]);
        __syncthreads();
    }
    float rmax = sred[0];
    __syncthreads();
    float s = expf(row[tid] - rmax) + expf(row[tid + 256] - rmax) + expf(row[tid + 512] - rmax);
    sred[tid] = s;
    __syncthreads();
    for (int st = 128; st > 0; st >>= 1) {
        if (tid < st) sred[tid] += sred[tid + st];
        __syncthreads();
    }
    if (tid == 0) g_lse[p] = rmax + logf(sred[0]);
}

__global__ __launch_bounds__(256) void combine_kernel(float* __restrict__ out) {
    const float* zp = (const float*)g_union;
    int b = blockIdx.y;
    int o = blockIdx.x * 256 + threadIdx.x;
    int p0 = g_tok_p[b * 2 + 0], p1 = g_tok_p[b * 2 + 1];
    float g0 = g_tok_g[b * 2 + 0], g1 = g_tok_g[b * 2 + 1];
    float lse0 = g_lse[p0], lse1 = g_lse[p1];
    float z0 = zp[(size_t)p0 * DOUT + o];
    float z1 = zp[(size_t)p1 * DOUT + o];
    float c = g0 * expf(z0 - lse0) + g1 * expf(z1 - lse1);
    if (c == 0.0f) c = 2.2204460492503131e-16f;
    out[(size_t)b * DOUT + o] = logf(c);
}

__global__ __launch_bounds__(256) void loss_kernel(float* __restrict__ out, int write_loss) {
    __shared__ float simp[NEXP][257];
    int tid = threadIdx.x;
#pragma unroll
    for (int e = 0; e < NEXP; e++) simp[e][tid] = 0.f;
    __syncthreads();
    for (int t = tid; t < BTOK; t += 256) {
        simp[g_tok_e[t * 2 + 0]][tid] += g_tok_g[t * 2 + 0];
        simp[g_tok_e[t * 2 + 1]][tid] += g_tok_g[t * 2 + 1];
    }
    __syncthreads();
    for (int st = 128; st > 0; st >>= 1) {
        if (tid < st)
#pragma unroll
            for (int e = 0; e < NEXP; e++) simp[e][tid] += simp[e][tid + st];
        __syncthreads();
    }
    if (tid == 0 && write_loss) {
        float mi = 0.f, ml = 0.f;
        for (int e = 0; e < NEXP; e++) { mi += simp[e][0]; ml += (float)g_cursor[e]; }
        mi /= NEXP; ml /= NEXP;
        float si = 0.f, sl = 0.f;
        for (int e = 0; e < NEXP; e++) {
            float di = simp[e][0] - mi;
            float dl = (float)g_cursor[e] - ml;
            si += di * di;
            sl += dl * dl;
        }
        si /= (NEXP - 1); sl /= (NEXP - 1);
        out[(size_t)BTOK * DOUT] = 0.01f * (si / (mi * mi + 1e-10f) + sl / (ml * ml + 1e-10f));
    }
}

// ---------------- launch ----------------
extern "C" void kernel_launch(void* const* d_in, const int* in_sizes, int n_in,
                              void* d_out, int out_size) {
    const float* x  = (const float*)d_in[0];
    const float* wg = (const float*)d_in[1];
    const float* W1 = (const float*)d_in[2];
    const float* b1 = (const float*)d_in[3];
    const float* W2 = (const float*)d_in[4];
    const float* b2 = (const float*)d_in[5];
    float* out = (float*)d_out;

    int write_loss = (out_size > BTOK * DOUT) ? 1 : 0;

    init_kernel<<<(MAXPAIR + 255) / 256, 256>>>();
    gating_kernel<<<(BTOK * 32 + 255) / 256, 256>>>(x, wg);
    offsets_kernel<<<1, 1>>>();
    assign_kernel<<<(BTOK + 255) / 256, 256>>>();
    gather_x<<<MAXPAIR / 16, 256>>>(x);
    gemm_frag<K16_1, DH, true><<<dim3(DH / 128, MAXMT), 512>>>(W1, b1);
    gemm_frag<K16_2, DOUT, false><<<dim3(DOUT / 128, MAXMT), 512>>>(W2, b2);
    lse_kernel<<<MAXPAIR, 256>>>();
    combine_kernel<<<dim3(DOUT / 256, BTOK), 256>>>(out);
    loss_kernel<<<1, 256>>>(out, write_loss);
}

// round 16
// speedup vs baseline: 2.0520x; 1.3051x over previous
#include <cuda_runtime.h>
#include <cuda_fp16.h>
#include <math.h>
#include <stdint.h>

// Problem constants
#define BTOK 4096
#define NEXP 8
#define DIN  768
#define DH   2048
#define DOUT 768
#define TOPK 2
#define MAXPAIR 9216
#define MAXMT   72
#define K16_1 48    // DIN/16
#define K16_2 128   // DH/16

// ---------------- device globals (~63 MiB total; < 128 MiB granule; NO cp.async/ldmatrix) ----------------
__device__ uint4 g_a2f[(size_t)(MAXPAIR / 16) * K16_2 * 32];   // A2 fp16 fragments (36 MB)
#define A1F_BYTES 14155776  // (MAXPAIR/16) * K16_1 * 32 * 16
__device__ __align__(16) unsigned char g_union[(size_t)MAXPAIR * DOUT * 4];  // A1 frags, then z
__device__ float g_lse[MAXPAIR];
__device__ int   g_pair_token[MAXPAIR];
__device__ int   g_count[NEXP];
__device__ int   g_cursor[NEXP];
__device__ int   g_off[NEXP + 1];
__device__ int   g_mtile_expert[MAXMT];
__device__ int   g_n_mtiles;
__device__ int   g_tok_e[BTOK * TOPK];
__device__ float g_tok_g[BTOK * TOPK];
__device__ int   g_tok_p[BTOK * TOPK];

// ---------------- PTX helpers ----------------
__device__ __forceinline__ uint32_t smem_u32(const void* p) {
    uint32_t a;
    asm("{ .reg .u64 t; cvta.to.shared.u64 t, %1; cvt.u32.u64 %0, t; }" : "=r"(a) : "l"(p));
    return a;
}
__device__ __forceinline__ void lds128v(uint4& v, uint32_t a) {
    asm volatile("ld.shared.v4.u32 {%0,%1,%2,%3}, [%4];"
                 : "=r"(v.x), "=r"(v.y), "=r"(v.z), "=r"(v.w) : "r"(a));
}
__device__ __forceinline__ void lds64v(uint2& v, uint32_t a) {
    asm volatile("ld.shared.v2.u32 {%0,%1}, [%2];" : "=r"(v.x), "=r"(v.y) : "r"(a));
}
__device__ __forceinline__ void sts128v(uint32_t a, uint4 v) {
    asm volatile("st.shared.v4.u32 [%0], {%1,%2,%3,%4};"
                 :: "r"(a), "r"(v.x), "r"(v.y), "r"(v.z), "r"(v.w));
}
__device__ __forceinline__ void sts32(uint32_t a, uint32_t v) {
    asm volatile("st.shared.u32 [%0], %1;" :: "r"(a), "r"(v));
}
__device__ __forceinline__ void mma16816(float& c0, float& c1, float& c2, float& c3,
                                         uint32_t a0, uint32_t a1, uint32_t a2, uint32_t a3,
                                         uint32_t b0, uint32_t b1) {
    asm volatile("mma.sync.aligned.m16n8k16.row.col.f32.f16.f16.f32 "
                 "{%0,%1,%2,%3}, {%4,%5,%6,%7}, {%8,%9}, {%0,%1,%2,%3};"
                 : "+f"(c0), "+f"(c1), "+f"(c2), "+f"(c3)
                 : "r"(a0), "r"(a1), "r"(a2), "r"(a3), "r"(b0), "r"(b1));
}
__device__ __forceinline__ uint32_t pack16(float a, float b) {
    __half2 hh = __floats2half2_rn(a, b);
    return *(uint32_t*)&hh;
}
__device__ __forceinline__ float gelu_tanh(float v) {
    float v3 = v * v * v;
    return 0.5f * v * (1.0f + tanhf(0.7978845608028654f * (v + 0.044715f * v3)));
}

// smem (static 16,640 B): A 8K | B 8448 (both single fp16)
#define AHI 0
#define BHI 8192
#define B_TILE_STRIDE 264
#define B_J_STRIDE 4224

// ---------------- small kernels ----------------
__global__ void init_kernel() {
    int i = blockIdx.x * blockDim.x + threadIdx.x;
    if (i < MAXPAIR) g_pair_token[i] = -1;
    if (i < NEXP) { g_count[i] = 0; g_cursor[i] = 0; }
}

__global__ void gating_kernel(const float* __restrict__ x, const float* __restrict__ wg) {
    int gthread = blockIdx.x * blockDim.x + threadIdx.x;
    int warp = gthread >> 5, lane = gthread & 31;
    if (warp >= BTOK) return;
    const float* xr = x + (size_t)warp * DIN;
    float a0 = 0.f, a1 = 0.f, a2 = 0.f, a3 = 0.f, a4 = 0.f, a5 = 0.f, a6 = 0.f, a7 = 0.f;
    for (int i = lane; i < DIN; i += 32) {
        float xv = xr[i];
        const float4* wr = (const float4*)(wg + (size_t)i * NEXP);
        float4 w0 = wr[0], w1 = wr[1];
        a0 += xv * w0.x; a1 += xv * w0.y; a2 += xv * w0.z; a3 += xv * w0.w;
        a4 += xv * w1.x; a5 += xv * w1.y; a6 += xv * w1.z; a7 += xv * w1.w;
    }
#pragma unroll
    for (int off = 16; off > 0; off >>= 1) {
        a0 += __shfl_down_sync(0xFFFFFFFFu, a0, off);
        a1 += __shfl_down_sync(0xFFFFFFFFu, a1, off);
        a2 += __shfl_down_sync(0xFFFFFFFFu, a2, off);
        a3 += __shfl_down_sync(0xFFFFFFFFu, a3, off);
        a4 += __shfl_down_sync(0xFFFFFFFFu, a4, off);
        a5 += __shfl_down_sync(0xFFFFFFFFu, a5, off);
        a6 += __shfl_down_sync(0xFFFFFFFFu, a6, off);
        a7 += __shfl_down_sync(0xFFFFFFFFu, a7, off);
    }
    if (lane == 0) {
        float v0 = -3.402823466e38f, v1 = -3.402823466e38f;
        int e0 = 0, e1 = 0;
#define TOP2(val, idx) { float v = (val); if (v > v0) { v1 = v0; e1 = e0; v0 = v; e0 = idx; } else if (v > v1) { v1 = v; e1 = idx; } }
        TOP2(a0, 0) TOP2(a1, 1) TOP2(a2, 2) TOP2(a3, 3)
        TOP2(a4, 4) TOP2(a5, 5) TOP2(a6, 6) TOP2(a7, 7)
#undef TOP2
        float ex = expf(v1 - v0);
        float inv = 1.0f / (1.0f + ex);
        g_tok_e[warp * 2 + 0] = e0; g_tok_e[warp * 2 + 1] = e1;
        g_tok_g[warp * 2 + 0] = inv; g_tok_g[warp * 2 + 1] = ex * inv;
        atomicAdd(&g_count[e0], 1);
        atomicAdd(&g_count[e1], 1);
    }
}

__global__ void offsets_kernel() {
    if (threadIdx.x != 0 || blockIdx.x != 0) return;
    int off = 0, nt = 0;
    for (int e = 0; e < NEXP; e++) {
        g_off[e] = off;
        int c = g_count[e];
        int tiles = (c + 127) >> 7;
        for (int t = 0; t < tiles; t++) g_mtile_expert[nt + t] = e;
        nt += tiles;
        off += tiles << 7;
    }
    g_off[NEXP] = off;
    g_n_mtiles = nt;
}

__global__ void assign_kernel() {
    int t = blockIdx.x * blockDim.x + threadIdx.x;
    if (t >= BTOK) return;
#pragma unroll
    for (int s = 0; s < TOPK; s++) {
        int e = g_tok_e[t * 2 + s];
        int pos = atomicAdd(&g_cursor[e], 1);
        int p = g_off[e] + pos;
        g_pair_token[p] = t;
        g_tok_p[t * 2 + s] = p;
    }
}

// ---------------- gather_x: pair rows -> A1 fp16 fragments in g_union ----------------
__global__ __launch_bounds__(256) void gather_x(const float* __restrict__ x) {
    __shared__ float s[16][260];
    uint4* a1f = (uint4*)g_union;
    int bt = blockIdx.x;
    int t = threadIdx.x;
    int wi = t >> 5, lane = t & 31;
    int fr = lane >> 2, fk = (lane & 3) * 2;
    for (int c = 0; c < 3; c++) {
#pragma unroll
        for (int r = 0; r < 16; r++) {
            int tok = g_pair_token[bt * 16 + r];
            s[r][t] = (tok >= 0) ? x[(size_t)tok * DIN + c * 256 + t] : 0.f;
        }
        __syncthreads();
#pragma unroll
        for (int sub = 0; sub < 2; sub++) {
            int ktl = wi * 2 + sub;
            int kb = ktl * 16;
            uint4 H;
            H.x = pack16(s[fr][kb + fk], s[fr][kb + fk + 1]);
            H.y = pack16(s[fr + 8][kb + fk], s[fr + 8][kb + fk + 1]);
            H.z = pack16(s[fr][kb + fk + 8], s[fr][kb + fk + 9]);
            H.w = pack16(s[fr + 8][kb + fk + 8], s[fr + 8][kb + fk + 9]);
            size_t ad = ((size_t)bt * K16_1 + c * 16 + ktl) * 32 + lane;
            a1f[ad] = H;
        }
        __syncthreads();
    }
}

// ---------------- GEMM: 512 threads, 16 warps 4(m)x4(n), warp tile 32x32, single-fp16 1-term ----------------
template<int K16T, int NB, bool ISG1>
__global__ __launch_bounds__(512) void gemm_frag(const float* __restrict__ W,
                                                 const float* __restrict__ bias) {
    int mt = blockIdx.y;
    if (mt >= g_n_mtiles) return;
    int e = g_mtile_expert[mt];
    int col0 = blockIdx.x << 7;

    __shared__ __align__(16) unsigned char sm[16640];
    uint32_t sb = smem_u32(sm);
    int tid = threadIdx.x, w = tid >> 5, lane = tid & 31;
    int wm16 = (w >> 2) * 2;   // m16 tile base (0/2/4/6)
    int wn8 = (w & 3) * 4;     // n8 tile base
    int wn = (w & 3) * 32;

    const uint4* Af = ISG1 ? (const uint4*)g_union : g_a2f;
    float* zp = (float*)g_union;

    // A staging: thread t covers uint4 #t of the chunk's 512 fragments
    int ai = tid >> 6, j_a = (tid >> 5) & 1;
    size_t aB = ((size_t)(mt * 8 + ai) * K16T + j_a) * 32 + (tid & 31);
    uint32_t dA = (uint32_t)(tid * 16);

    // B staging: thread -> k-pair kp=(tid>>5)*2 (0..30), 4 n columns (single fp16)
    int kp = (tid >> 5) * 2;
    int nseg4 = tid & 31;
    int nt = nseg4 >> 1;
    int ncol0 = (nseg4 & 1) * 4;
    int j_b = kp >> 4;
    int rem = kp & 15;
    uint32_t comp = (rem >= 8) ? 4u : 0u;
    int lq = (rem & 7) >> 1;
    uint32_t dB = (uint32_t)(BHI + j_b * B_J_STRIDE + nt * B_TILE_STRIDE + ncol0 * 32 + lq * 8) + comp;
    const float* bw = W + ((size_t)e * (K16T * 16) + kp) * NB + col0 + nt * 8 + ncol0;

    // compute-phase bases
    uint32_t aF = sb + AHI + (uint32_t)(lane * 16);
    uint32_t bF = sb + BHI + (uint32_t)(lane * 8);

#define DECL_ACC(mi, ni) float c##mi##ni##0 = 0.f, c##mi##ni##1 = 0.f, c##mi##ni##2 = 0.f, c##mi##ni##3 = 0.f;
    DECL_ACC(0, 0) DECL_ACC(0, 1) DECL_ACC(0, 2) DECL_ACC(0, 3)
    DECL_ACC(1, 0) DECL_ACC(1, 1) DECL_ACC(1, 2) DECL_ACC(1, 3)
#undef DECL_ACC

    uint4 pah;
    float4 pb0, pb1;
#define PREFETCH(ck) do { \
    pah = Af[aB + (size_t)(ck) * 64]; \
    const float* p_ = bw + (size_t)(ck) * 32 * NB; \
    pb0 = *(const float4*)(p_); \
    pb1 = *(const float4*)(p_ + NB); \
} while (0)
#define BSTS(i, va, vb) sts32(sb + dB + (i) * 32, pack16(va, vb))
#define STAGE() do { \
    sts128v(sb + dA, pah); \
    BSTS(0, pb0.x, pb1.x); BSTS(1, pb0.y, pb1.y); \
    BSTS(2, pb0.z, pb1.z); BSTS(3, pb0.w, pb1.w); \
} while (0)
#define MMA1(mi, ni) \
    mma16816(c##mi##ni##0, c##mi##ni##1, c##mi##ni##2, c##mi##ni##3, \
             ah##mi.x, ah##mi.y, ah##mi.z, ah##mi.w, bh##ni.x, bh##ni.y);
#define COMPUTE_J(j) do { \
    uint4 ah0, ah1; \
    uint2 bh0, bh1, bh2, bh3; \
    lds128v(ah0, aF + ((wm16 + 0) * 2 + (j)) * 512); \
    lds128v(ah1, aF + ((wm16 + 1) * 2 + (j)) * 512); \
    lds64v(bh0, bF + (j) * B_J_STRIDE + (wn8 + 0) * B_TILE_STRIDE); \
    lds64v(bh1, bF + (j) * B_J_STRIDE + (wn8 + 1) * B_TILE_STRIDE); \
    lds64v(bh2, bF + (j) * B_J_STRIDE + (wn8 + 2) * B_TILE_STRIDE); \
    lds64v(bh3, bF + (j) * B_J_STRIDE + (wn8 + 3) * B_TILE_STRIDE); \
    MMA1(0, 0) MMA1(0, 1) MMA1(0, 2) MMA1(0, 3) \
    MMA1(1, 0) MMA1(1, 1) MMA1(1, 2) MMA1(1, 3) \
} while (0)

    const int NC = K16T / 2;
    PREFETCH(0);
    for (int ck = 0; ck < NC; ck++) {
        STAGE();
        __syncthreads();
        if (ck + 1 < NC) PREFETCH(ck + 1);
        COMPUTE_J(0);
        COMPUTE_J(1);
        __syncthreads();
    }
#undef PREFETCH
#undef BSTS
#undef STAGE
#undef COMPUTE_J
#undef MMA1

    // ---- epilogue ----
    int er = lane >> 2;
    int ec = (lane & 3) * 2;
#define EPI(mi) do { \
    if (ISG1) { \
        size_t m16o = (size_t)(mt * 8 + wm16 + (mi)); \
        int gc0 = col0 + wn + ec; \
        { \
            float bE0 = __ldg(bias + (size_t)e * DH + gc0); \
            float bE1 = __ldg(bias + (size_t)e * DH + gc0 + 1); \
            float bO0 = __ldg(bias + (size_t)e * DH + gc0 + 8); \
            float bO1 = __ldg(bias + (size_t)e * DH + gc0 + 9); \
            uint4 H; \
            H.x = pack16(gelu_tanh(c##mi##00 + bE0), gelu_tanh(c##mi##01 + bE1)); \
            H.y = pack16(gelu_tanh(c##mi##02 + bE0), gelu_tanh(c##mi##03 + bE1)); \
            H.z = pack16(gelu_tanh(c##mi##10 + bO0), gelu_tanh(c##mi##11 + bO1)); \
            H.w = pack16(gelu_tanh(c##mi##12 + bO0), gelu_tanh(c##mi##13 + bO1)); \
            size_t ad = (m16o * K16_2 + (size_t)((col0 + wn) >> 4)) * 32 + lane; \
            g_a2f[ad] = H; \
        } \
        { \
            float bE0 = __ldg(bias + (size_t)e * DH + gc0 + 16); \
            float bE1 = __ldg(bias + (size_t)e * DH + gc0 + 17); \
            float bO0 = __ldg(bias + (size_t)e * DH + gc0 + 24); \
            float bO1 = __ldg(bias + (size_t)e * DH + gc0 + 25); \
            uint4 H; \
            H.x = pack16(gelu_tanh(c##mi##20 + bE0), gelu_tanh(c##mi##21 + bE1)); \
            H.y = pack16(gelu_tanh(c##mi##22 + bE0), gelu_tanh(c##mi##23 + bE1)); \
            H.z = pack16(gelu_tanh(c##mi##30 + bO0), gelu_tanh(c##mi##31 + bO1)); \
            H.w = pack16(gelu_tanh(c##mi##32 + bO0), gelu_tanh(c##mi##33 + bO1)); \
            size_t ad = (m16o * K16_2 + (size_t)(((col0 + wn) >> 4) + 1)) * 32 + lane; \
            g_a2f[ad] = H; \
        } \
    } else { \
        int rb = mt * 128 + (wm16 + (mi)) * 16 + er; \
        int gcb = col0 + wn + ec; \
        float b0v = __ldg(bias + (size_t)e * DOUT + gcb); \
        float b1v = __ldg(bias + (size_t)e * DOUT + gcb + 1); \
        float b8v = __ldg(bias + (size_t)e * DOUT + gcb + 8); \
        float b9v = __ldg(bias + (size_t)e * DOUT + gcb + 9); \
        float b16v = __ldg(bias + (size_t)e * DOUT + gcb + 16); \
        float b17v = __ldg(bias + (size_t)e * DOUT + gcb + 17); \
        float b24v = __ldg(bias + (size_t)e * DOUT + gcb + 24); \
        float b25v = __ldg(bias + (size_t)e * DOUT + gcb + 25); \
        float2 o; \
        o.x = c##mi##00 + b0v;  o.y = c##mi##01 + b1v;  *(float2*)(zp + (size_t)rb * DOUT + gcb) = o; \
        o.x = c##mi##02 + b0v;  o.y = c##mi##03 + b1v;  *(float2*)(zp + (size_t)(rb + 8) * DOUT + gcb) = o; \
        o.x = c##mi##10 + b8v;  o.y = c##mi##11 + b9v;  *(float2*)(zp + (size_t)rb * DOUT + gcb + 8) = o; \
        o.x = c##mi##12 + b8v;  o.y = c##mi##13 + b9v;  *(float2*)(zp + (size_t)(rb + 8) * DOUT + gcb + 8) = o; \
        o.x = c##mi##20 + b16v; o.y = c##mi##21 + b17v; *(float2*)(zp + (size_t)rb * DOUT + gcb + 16) = o; \
        o.x = c##mi##22 + b16v; o.y = c##mi##23 + b17v; *(float2*)(zp + (size_t)(rb + 8) * DOUT + gcb + 16) = o; \
        o.x = c##mi##30 + b24v; o.y = c##mi##31 + b25v; *(float2*)(zp + (size_t)rb * DOUT + gcb + 24) = o; \
        o.x = c##mi##32 + b24v; o.y = c##mi##33 + b25v; *(float2*)(zp + (size_t)(rb + 8) * DOUT + gcb + 24) = o; \
    } \
} while (0)
    EPI(0); EPI(1);
#undef EPI
}

// ---------------- logsumexp / combine / loss (z lives in g_union) ----------------
__global__ __launch_bounds__(256) void lse_kernel() {
    int p = blockIdx.x;
    if (g_pair_token[p] < 0) return;
    const float* row = (const float*)g_union + (size_t)p * DOUT;
    int tid = threadIdx.x;
    __shared__ float sred[256];
    float m = fmaxf(fmaxf(row[tid], row[tid + 256]), row[tid + 512]);
    sred[tid] = m;
    __syncthreads();
    for (int st = 128; st > 0; st >>= 1) {
        if (tid < st) sred[tid] = fmaxf(sred[tid], sred[tid + st]);
        __syncthreads();
    }
    float rmax = sred[0];
    __syncthreads();
    float s = expf(row[tid] - rmax) + expf(row[tid + 256] - rmax) + expf(row[tid + 512] - rmax);
    sred[tid] = s;
    __syncthreads();
    for (int st = 128; st > 0; st >>= 1) {
        if (tid < st) sred[tid] += sred[tid + st];
        __syncthreads();
    }
    if (tid == 0) g_lse[p] = rmax + logf(sred[0]);
}

__global__ __launch_bounds__(256) void combine_kernel(float* __restrict__ out) {
    const float* zp = (const float*)g_union;
    int b = blockIdx.y;
    int o = blockIdx.x * 256 + threadIdx.x;
    int p0 = g_tok_p[b * 2 + 0], p1 = g_tok_p[b * 2 + 1];
    float g0 = g_tok_g[b * 2 + 0], g1 = g_tok_g[b * 2 + 1];
    float lse0 = g_lse[p0], lse1 = g_lse[p1];
    float z0 = zp[(size_t)p0 * DOUT + o];
    float z1 = zp[(size_t)p1 * DOUT + o];
    float c = g0 * expf(z0 - lse0) + g1 * expf(z1 - lse1);
    if (c == 0.0f) c = 2.2204460492503131e-16f;
    out[(size_t)b * DOUT + o] = logf(c);
}

__global__ __launch_bounds__(256) void loss_kernel(float* __restrict__ out, int write_loss) {
    __shared__ float simp[NEXP][257];
    int tid = threadIdx.x;
#pragma unroll
    for (int e = 0; e < NEXP; e++) simp[e][tid] = 0.f;
    __syncthreads();
    for (int t = tid; t < BTOK; t += 256) {
        simp[g_tok_e[t * 2 + 0]][tid] += g_tok_g[t * 2 + 0];
        simp[g_tok_e[t * 2 + 1]][tid] += g_tok_g[t * 2 + 1];
    }
    __syncthreads();
    for (int st = 128; st > 0; st >>= 1) {
        if (tid < st)
#pragma unroll
            for (int e = 0; e < NEXP; e++) simp[e][tid] += simp[e][tid + st];
        __syncthreads();
    }
    if (tid == 0 && write_loss) {
        float mi = 0.f, ml = 0.f;
        for (int e = 0; e < NEXP; e++) { mi += simp[e][0]; ml += (float)g_cursor[e]; }
        mi /= NEXP; ml /= NEXP;
        float si = 0.f, sl = 0.f;
        for (int e = 0; e < NEXP; e++) {
            float di = simp[e][0] - mi;
            float dl = (float)g_cursor[e] - ml;
            si += di * di;
            sl += dl * dl;
        }
        si /= (NEXP - 1); sl /= (NEXP - 1);
        out[(size_t)BTOK * DOUT] = 0.01f * (si / (mi * mi + 1e-10f) + sl / (ml * ml + 1e-10f));
    }
}

// ---------------- launch ----------------
extern "C" void kernel_launch(void* const* d_in, const int* in_sizes, int n_in,
                              void* d_out, int out_size) {
    const float* x  = (const float*)d_in[0];
    const float* wg = (const float*)d_in[1];
    const float* W1 = (const float*)d_in[2];
    const float* b1 = (const float*)d_in[3];
    const float* W2 = (const float*)d_in[4];
    const float* b2 = (const float*)d_in[5];
    float* out = (float*)d_out;

    int write_loss = (out_size > BTOK * DOUT) ? 1 : 0;

    init_kernel<<<(MAXPAIR + 255) / 256, 256>>>();
    gating_kernel<<<(BTOK * 32 + 255) / 256, 256>>>(x, wg);
    offsets_kernel<<<1, 1>>>();
    assign_kernel<<<(BTOK + 255) / 256, 256>>>();
    gather_x<<<MAXPAIR / 16, 256>>>(x);
    gemm_frag<K16_1, DH, true><<<dim3(DH / 128, MAXMT), 512>>>(W1, b1);
    gemm_frag<K16_2, DOUT, false><<<dim3(DOUT / 128, MAXMT), 512>>>(W2, b2);
    lse_kernel<<<MAXPAIR, 256>>>();
    combine_kernel<<<dim3(DOUT / 256, BTOK), 256>>>(out);
    loss_kernel<<<1, 256>>>(out, write_loss);
}